// round 1
// baseline (speedup 1.0000x reference)
#include <cuda_runtime.h>

// Output element out[((b*H + y)*W + x)*C*16 + ch*16 + i*4 + j]
//   = in[b, ch, y+i-3, x+j-2]   (zero if out of range, or if i==3 && j>=2)
// Shapes: B=8, C=192, H=W=48. One thread produces one float4 (the j=0..3 group).

#define B_ 8
#define C_ 192
#define H_ 48
#define W_ 48

__global__ void __launch_bounds__(256)
block_sample_kernel(const float* __restrict__ in, float* __restrict__ out, int total4)
{
    int tid = blockIdx.x * blockDim.x + threadIdx.x;
    if (tid >= total4) return;

    // decode: tid = (((b*H + y)*W + x)*C + ch)*4 + i
    int i  = tid & 3;
    int t  = tid >> 2;
    int ch = t % C_;  t /= C_;
    int x  = t % W_;  t /= W_;
    int y  = t % H_;
    int b  = t / H_;

    int row = y + i - 3;
    float4 v = make_float4(0.f, 0.f, 0.f, 0.f);

    if (row >= 0 && row < H_) {
        const float* p = in + ((((long)b * C_ + ch) * H_ + row) * W_);
        int c0 = x - 2;                 // column for j=0
        if (c0 >= 0)      v.x = __ldg(p + c0);      // j=0 (c0 <= 45 always)
        if (c0 + 1 >= 0)  v.y = __ldg(p + c0 + 1);  // j=1 (<= 46 always)
                          v.z = __ldg(p + c0 + 2);  // j=2 (== x, always in range)
        if (c0 + 3 < W_)  v.w = __ldg(p + c0 + 3);  // j=3 (>= 1 always)
    }

    // masked taps: (i==3, j==2) and (i==3, j==3)
    if (i == 3) { v.z = 0.f; v.w = 0.f; }

    reinterpret_cast<float4*>(out)[tid] = v;
}

extern "C" void kernel_launch(void* const* d_in, const int* in_sizes, int n_in,
                              void* d_out, int out_size)
{
    const float* in  = (const float*)d_in[0];
    float*       out = (float*)d_out;

    int total4 = out_size / 4;           // 14,155,776 float4 stores
    int threads = 256;
    int blocks  = (total4 + threads - 1) / threads;
    block_sample_kernel<<<blocks, threads>>>(in, out, total4);
}

// round 2
// speedup vs baseline: 2.2060x; 2.2060x over previous
#include <cuda_runtime.h>

// out[((b*H+y)*W+x)*C*16 + ch*16 + i*4 + j] = in[b,ch, y+i-3, x+j-2]
// zero outside, and taps (i==3, j>=2) masked.
// B=8, C=192, H=W=48.
// Block = (b, y, x-tile of 8). Smem tile: [192 ch][4 rows][11 cols], pitch 11.

#define B_  8
#define C_  192
#define H_  48
#define W_  48
#define TX  8
#define XT  (W_ / TX)            // 6 x-tiles per row
#define PITCH 11                 // TX + 3 cols (x0-2 .. x0+8)
#define SROWS (C_ * 4)           // 768 (ch,row) segments
#define SELEMS (SROWS * PITCH)   // 8448 floats = 33792 B
#define NOUT4 (TX * C_ * 4)      // 6144 float4 per block

__global__ void __launch_bounds__(256)
block_sample_smem(const float* __restrict__ in, float4* __restrict__ out)
{
    __shared__ float s[SELEMS];

    const int tid = threadIdx.x;
    int bid = blockIdx.x;
    const int xt = bid % XT;  bid /= XT;
    const int y  = bid % H_;
    const int b  = bid / H_;
    const int x0 = xt * TX;

    // ---- load phase: rows y-3..y, cols x0-2..x0+8, all channels ----
    #pragma unroll 4
    for (int idx = tid; idx < SELEMS; idx += 256) {
        const int sc = idx % PITCH;          // 0..10
        const int rf = idx / PITCH;          // ch*4 + r
        const int ch = rf >> 2;
        const int r  = rf & 3;
        const int gy = y + r - 3;            // gy <= 47 always
        const int gx = x0 - 2 + sc;          // may be -2..48
        float v = 0.f;
        if (gy >= 0 && gx >= 0 && gx < W_)
            v = __ldg(in + ((b * C_ + ch) * H_ + gy) * W_ + gx);
        s[idx] = v;
    }
    __syncthreads();

    // ---- store phase: one float4 (j=0..3) per iteration per thread ----
    // idx = xl*768 + ch*4 + i  (i fastest -> consecutive out float4s)
    const long posbase = ((long)((b * H_ + y) * W_ + x0)) * (C_ * 4);
    #pragma unroll 4
    for (int idx = tid; idx < NOUT4; idx += 256) {
        const int i   = idx & 3;
        const int chi = idx >> 2;
        const int ch  = chi % C_;
        const int xl  = chi / C_;
        const float* row = &s[(ch * 4 + i) * PITCH + xl];
        float4 v;
        v.x = row[0];
        v.y = row[1];
        v.z = (i == 3) ? 0.f : row[2];
        v.w = (i == 3) ? 0.f : row[3];
        out[posbase + (long)xl * (C_ * 4) + idx - xl * (C_ * 4)] = v;
    }
}

extern "C" void kernel_launch(void* const* d_in, const int* in_sizes, int n_in,
                              void* d_out, int out_size)
{
    const float* in  = (const float*)d_in[0];
    float4*      out = (float4*)d_out;

    const int blocks = B_ * H_ * XT;   // 2304
    block_sample_smem<<<blocks, 256>>>(in, out);
}

// round 3
// speedup vs baseline: 2.6393x; 1.1964x over previous
#include <cuda_runtime.h>

// out[((b*H+y)*W+x)*C*16 + ch*16 + i*4 + j] = in[b, ch, y+i-3, x+j-2]
// zero outside, taps (i==3, j>=2) masked. B=8, C=192, H=W=48.
// Block = (b, y, x-tile of 4). Smem: [192 ch * 4 rows][pitch 7 cols] = 21504 B.

#define B_   8
#define C_   192
#define H_   48
#define W_   48
#define TX   4
#define XT   (W_ / TX)           // 12 x-tiles per row
#define PITCH 7                  // TX + 3 cols (x0-2 .. x0+4)
#define SROWS (C_ * 4)           // 768 (ch,row) segments
#define SELEMS (SROWS * PITCH)   // 5376 floats = 21504 B
#define LOAD_ITERS (SELEMS / 256)  // 21 exactly

__global__ void __launch_bounds__(256)
block_sample_smem(const float* __restrict__ in, float4* __restrict__ out)
{
    __shared__ float s[SELEMS];

    const int tid = threadIdx.x;
    int bid = blockIdx.x;
    const int xt = bid % XT;  bid /= XT;
    const int y  = bid % H_;
    const int b  = bid / H_;
    const int x0 = xt * TX;

    // ---- load phase: rows y-3..y, cols x0-2..x0+4, all 192 channels ----
    #pragma unroll
    for (int k = 0; k < LOAD_ITERS; k++) {
        const int idx = k * 256 + tid;
        const int sc  = idx % PITCH;      // 0..6 (magic-mul, no real div)
        const int rf  = idx / PITCH;      // ch*4 + r
        const int gy  = y + (rf & 3) - 3; // <= 47 always
        const int gx  = x0 - 2 + sc;      // -2..48
        float v = 0.f;
        if (gy >= 0 && gx >= 0 && gx < W_)
            v = __ldg(in + ((b * C_ + (rf >> 2)) * H_ + gy) * W_ + gx);
        s[idx] = v;
    }
    __syncthreads();

    // ---- store phase: 12 float4 stores per thread, fully unrolled ----
    // out float4 index = ((b*H+y)*W + x0+xl)*768 + ch*4+i = posbase + xl*768 + chi
    const long posbase = ((long)((b * H_ + y) * W_ + x0)) * (C_ * 4);
    #pragma unroll
    for (int xl = 0; xl < TX; xl++) {
        #pragma unroll
        for (int sub = 0; sub < 3; sub++) {             // 768 = 3*256
            const int chi = sub * 256 + tid;            // ch*4 + i
            const int i   = chi & 3;
            const float* row = &s[chi * PITCH + xl];
            float4 v;
            v.x = row[0];
            v.y = row[1];
            v.z = (i == 3) ? 0.f : row[2];
            v.w = (i == 3) ? 0.f : row[3];
            out[posbase + xl * (C_ * 4) + chi] = v;
        }
    }
}

extern "C" void kernel_launch(void* const* d_in, const int* in_sizes, int n_in,
                              void* d_out, int out_size)
{
    const float* in  = (const float*)d_in[0];
    float4*      out = (float4*)d_out;

    const int blocks = B_ * H_ * XT;   // 4608
    block_sample_smem<<<blocks, 256>>>(in, out);
}